// round 14
// baseline (speedup 1.0000x reference)
#include <cuda_runtime.h>
#include <cuda_fp16.h>
#include <cstdint>

#define SEQ     8
#define HDIM    512
#define HOUT    256
#define LN_EPS  1e-5f

// Transposed + fp16-rounded out_W: [256, 512] (n-major, k-contiguous).
__device__ __half g_Bt[(size_t)HOUT * HDIM];

// ---------------------------------------------------------------------------
// Helpers
// ---------------------------------------------------------------------------
__device__ __forceinline__ void mma_fp16(float* d, const uint32_t* a, const uint32_t* b) {
    asm volatile(
        "mma.sync.aligned.m16n8k16.row.col.f32.f16.f16.f32 "
        "{%0,%1,%2,%3}, {%4,%5,%6,%7}, {%8,%9}, {%0,%1,%2,%3};"
        : "+f"(d[0]), "+f"(d[1]), "+f"(d[2]), "+f"(d[3])
        : "r"(a[0]), "r"(a[1]), "r"(a[2]), "r"(a[3]), "r"(b[0]), "r"(b[1]));
}

// ---------------------------------------------------------------------------
// Transpose out_W [512,256] -> g_Bt [256,512] fp16.
// ---------------------------------------------------------------------------
__global__ __launch_bounds__(256) void transpose_B_kernel(const float* __restrict__ B) {
    __shared__ float tile[32][33];
    const int n0 = blockIdx.x * 32;
    const int k0 = blockIdx.y * 32;
    const int tx = threadIdx.x & 31;
    const int ty = threadIdx.x >> 5;
    #pragma unroll
    for (int i = 0; i < 32; i += 8)
        tile[ty + i][tx] = B[(size_t)(k0 + ty + i) * HOUT + n0 + tx];
    __syncthreads();
    #pragma unroll
    for (int i = 0; i < 32; i += 8) {
        g_Bt[(size_t)(n0 + ty + i) * HDIM + k0 + tx] = __float2half_rn(tile[tx][ty + i]);
    }
}

// ---------------------------------------------------------------------------
// FUSED kernel: LN + attention pooling + GEMM + bias + relu.
// CTA = 256 threads owns 64 rows.
//   Phase 1 (LN): 32 iterations x 2 rows (v6 math: thread owns 4 cols,
//     batched reduce-scatter, 8-lane softmax). fp16 result written straight
//     into the smem A tile (row stride 1088 B => conflict-free fragments).
//   Phase 2 (GEMM): C[64,256] = relu(A @ Bt^T + bias). A fragments via LDS
//     from the tile; B fragments via direct LDG from L2-resident g_Bt
//     (each B value is read by exactly one warp -> no amplification).
//     No smem staging, no pipeline barriers.
// ---------------------------------------------------------------------------
#define ROWS_PER_CTA 64
#define LN_ITERS     (ROWS_PER_CTA / 2)
#define A_ROW_BYTES  1088                        // 68 x 16B units (68%8==4 -> conflict-free)
#define A_SMEM_BYTES (ROWS_PER_CTA * A_ROW_BYTES)  // 69632
#define BKH          32                          // halfs per k-chunk
#define NCH          (HDIM / BKH)                // 16

__global__ __launch_bounds__(256, 2) void fused_kernel(
    const float* __restrict__ x,
    const float* __restrict__ gamma,
    const float* __restrict__ beta,
    const float* __restrict__ attnW,
    const float* __restrict__ bias,
    float* __restrict__ C)
{
    extern __shared__ char smem[];   // A tile, 64 x 1088 B

    __shared__ float s_red[2][4][26];
    __shared__ float s_k[2][8];
    __shared__ float s_K[2];

    const int tid  = threadIdx.x;
    const int w    = tid >> 5;
    const int lane = tid & 31;
    const int bm   = blockIdx.x;

    // ---- LN-phase thread mapping (v6): 2 rows x 4 warps; thread owns 4 cols.
    const int rloc = w >> 2;                 // 0..1
    const int slab = w & 3;                  // 0..3
    const int c4   = slab * 32 + lane;       // float4 column 0..127
    const int col  = c4 * 4;

    const float4 gv = *reinterpret_cast<const float4*>(gamma + col);
    const float4 wn = *reinterpret_cast<const float4*>(attnW + HDIM + col);
    float4 gw;
    gw.x = gv.x * wn.x; gw.y = gv.y * wn.y; gw.z = gv.z * wn.z; gw.w = gv.w * wn.w;
    const float4 bv = *reinterpret_cast<const float4*>(beta + col);
    const float s1_local = (gw.x + gw.y) + (gw.z + gw.w);

    // =======================  Phase 1: LN + pooling  =======================
    #pragma unroll 1
    for (int it = 0; it < LN_ITERS; it++) {
        const int lr = it * 2 + rloc;                         // local row 0..63
        const size_t row = (size_t)bm * ROWS_PER_CTA + lr;
        const float4* xr = reinterpret_cast<const float4*>(x + row * SEQ * HDIM);

        float4 xv[SEQ];
        float vals[32];
        #pragma unroll
        for (int t = 0; t < SEQ; t++) {
            const float4 v = xr[t * (HDIM / 4) + c4];
            xv[t] = v;
            vals[t]      = (v.x + v.y) + (v.z + v.w);
            vals[8 + t]  = (v.x * v.x + v.y * v.y) + (v.z * v.z + v.w * v.w);
            vals[16 + t] = (gw.x * v.x + gw.y * v.y) + (gw.z * v.z + gw.w * v.w);
        }
        vals[24] = s1_local;
        #pragma unroll
        for (int j = 25; j < 32; j++) vals[j] = 0.f;

        // Batched reduce-scatter: lane l ends with warp-total of quantity l.
        #pragma unroll
        for (int bit = 16; bit >= 1; bit >>= 1) {
            #pragma unroll
            for (int j = 0; j < bit; j++) {
                const bool hi = (lane & bit) != 0;
                const float keep = hi ? vals[j + bit] : vals[j];
                const float send = hi ? vals[j] : vals[j + bit];
                vals[j] = keep + __shfl_xor_sync(0xffffffffu, send, bit);
            }
        }

        if (lane < 25) s_red[rloc][slab][lane] = vals[0];
        __syncthreads();

        if ((w & 3) == 0) {
            const int r = rloc;
            float v = 0.f;
            if (lane < 25) {
                #pragma unroll
                for (int sl = 0; sl < 4; sl++) v += s_red[r][sl][lane];
            }
            const int t = lane & 7;
            const float S  = __shfl_sync(0xffffffffu, v, t);
            const float Q  = __shfl_sync(0xffffffffu, v, 8 + t);
            const float P  = __shfl_sync(0xffffffffu, v, 16 + t);
            const float S1 = __shfl_sync(0xffffffffu, v, 24);

            const float m    = S * (1.f / HDIM);
            const float var  = Q * (1.f / HDIM) - m * m;
            const float rstd = rsqrtf(var + LN_EPS);

            float logit = (lane >= 1 && lane < 8) ? rstd * (P - m * S1) : -1e30f;

            float mx = logit;
            mx = fmaxf(mx, __shfl_xor_sync(0xffffffffu, mx, 1));
            mx = fmaxf(mx, __shfl_xor_sync(0xffffffffu, mx, 2));
            mx = fmaxf(mx, __shfl_xor_sync(0xffffffffu, mx, 4));
            const float e = __expf(logit - mx);
            float se = e;
            se += __shfl_xor_sync(0xffffffffu, se, 1);
            se += __shfl_xor_sync(0xffffffffu, se, 2);
            se += __shfl_xor_sync(0xffffffffu, se, 4);
            const float a = e / se;

            const float kk = (lane == 0) ? rstd : a * rstd;
            float Km = kk * m;
            Km += __shfl_xor_sync(0xffffffffu, Km, 1);
            Km += __shfl_xor_sync(0xffffffffu, Km, 2);
            Km += __shfl_xor_sync(0xffffffffu, Km, 4);

            if (lane < 8) s_k[r][lane] = kk;
            if (lane == 0) s_K[r] = Km;
        }
        __syncthreads();

        const float Kc = s_K[rloc];
        float4 acc = make_float4(0.f, 0.f, 0.f, 0.f);
        #pragma unroll
        for (int t = 0; t < SEQ; t++) {
            const float kk = s_k[rloc][t];
            acc.x += kk * xv[t].x;
            acc.y += kk * xv[t].y;
            acc.z += kk * xv[t].z;
            acc.w += kk * xv[t].w;
        }
        const __half2 o0 = __floats2half2_rn(gv.x * (acc.x - Kc) + 2.f * bv.x,
                                             gv.y * (acc.y - Kc) + 2.f * bv.y);
        const __half2 o1 = __floats2half2_rn(gv.z * (acc.z - Kc) + 2.f * bv.z,
                                             gv.w * (acc.w - Kc) + 2.f * bv.w);
        uint2 o;
        o.x = *reinterpret_cast<const uint32_t*>(&o0);
        o.y = *reinterpret_cast<const uint32_t*>(&o1);
        *reinterpret_cast<uint2*>(smem + lr * A_ROW_BYTES + col * 2) = o;
    }
    __syncthreads();   // A tile complete

    // =======================  Phase 2: GEMM  ===============================
    // 8 warps as 2x4: warp_m in {0,1} (32 rows), warp_n in {0..3} (64 cols).
    const int warp_m = w & 1;
    const int warp_n = w >> 1;
    const int g  = lane >> 2;
    const int tg = lane & 3;

    const __half* Bg = g_Bt;

    float acc[2][8][4];
    #pragma unroll
    for (int mt = 0; mt < 2; mt++)
        #pragma unroll
        for (int nt = 0; nt < 8; nt++)
            #pragma unroll
            for (int i = 0; i < 4; i++) acc[mt][nt][i] = 0.f;

    #pragma unroll 1
    for (int k = 0; k < NCH; k++) {
        // B fragments: 8 x LDG.128 from L2-resident g_Bt, issued first.
        uint32_t bw[8][4];
        #pragma unroll
        for (int j = 0; j < 8; j++) {
            const int n = warp_n * 64 + j * 8 + g;
            const uint4 v = *reinterpret_cast<const uint4*>(
                Bg + (size_t)n * HDIM + k * BKH + tg * 8);
            bw[j][0] = v.x; bw[j][1] = v.y; bw[j][2] = v.z; bw[j][3] = v.w;
        }
        // A fragments: 4 x LDS.128 from the padded tile.
        uint32_t aw[2][2][4];
        #pragma unroll
        for (int mt = 0; mt < 2; mt++) {
            #pragma unroll
            for (int h = 0; h < 2; h++) {
                const int r = warp_m * 32 + mt * 16 + g + h * 8;
                const uint4 v = *reinterpret_cast<const uint4*>(
                    smem + r * A_ROW_BYTES + k * 64 + tg * 16);
                aw[mt][h][0] = v.x; aw[mt][h][1] = v.y;
                aw[mt][h][2] = v.z; aw[mt][h][3] = v.w;
            }
        }
        #pragma unroll
        for (int grp = 0; grp < 2; grp++) {
            #pragma unroll
            for (int mt = 0; mt < 2; mt++) {
                #pragma unroll
                for (int nt = 0; nt < 8; nt++) {
                    uint32_t a[4] = { aw[mt][0][grp * 2 + 0],
                                      aw[mt][1][grp * 2 + 0],
                                      aw[mt][0][grp * 2 + 1],
                                      aw[mt][1][grp * 2 + 1] };
                    uint32_t b[2] = { bw[nt][grp * 2 + 0],
                                      bw[nt][grp * 2 + 1] };
                    mma_fp16(acc[mt][nt], a, b);
                }
            }
        }
    }

    // Epilogue: bias + relu.
    const int row_base = bm * ROWS_PER_CTA + warp_m * 32;
    const int col_base = warp_n * 64;
    #pragma unroll
    for (int mt = 0; mt < 2; mt++) {
        #pragma unroll
        for (int nt = 0; nt < 8; nt++) {
            const int r0 = row_base + mt * 16 + g;
            const int c0 = col_base + nt * 8 + 2 * tg;
            const float2 bb = *reinterpret_cast<const float2*>(bias + c0);
            float2 o0, o1;
            o0.x = fmaxf(acc[mt][nt][0] + bb.x, 0.f);
            o0.y = fmaxf(acc[mt][nt][1] + bb.y, 0.f);
            o1.x = fmaxf(acc[mt][nt][2] + bb.x, 0.f);
            o1.y = fmaxf(acc[mt][nt][3] + bb.y, 0.f);
            *reinterpret_cast<float2*>(C + (size_t)r0 * HOUT + c0) = o0;
            *reinterpret_cast<float2*>(C + (size_t)(r0 + 8) * HOUT + c0) = o1;
        }
    }
}

// ---------------------------------------------------------------------------
extern "C" void kernel_launch(void* const* d_in, const int* in_sizes, int n_in,
                              void* d_out, int out_size) {
    const float* x     = (const float*)d_in[0];   // [N, 8, 512]
    const float* gamma = (const float*)d_in[1];   // [512]
    const float* beta  = (const float*)d_in[2];   // [512]
    const float* attnW = (const float*)d_in[3];   // [1024, 1]
    // d_in[4] = attn_b: cancels in softmax.
    const float* outW  = (const float*)d_in[5];   // [512, 256]
    const float* outb  = (const float*)d_in[6];   // [256]
    float* out = (float*)d_out;                   // [N, 256]

    const int n = in_sizes[0] / (SEQ * HDIM);

    cudaFuncSetAttribute(fused_kernel,
                         cudaFuncAttributeMaxDynamicSharedMemorySize, A_SMEM_BYTES);

    transpose_B_kernel<<<dim3(HOUT / 32, HDIM / 32), 256>>>(outW);
    fused_kernel<<<n / ROWS_PER_CTA, 256, A_SMEM_BYTES>>>(
        x, gamma, beta, attnW, outb, out);
}

// round 15
// speedup vs baseline: 1.0611x; 1.0611x over previous
#include <cuda_runtime.h>
#include <cuda_fp16.h>
#include <cstdint>

#define SEQ     8
#define HDIM    512
#define HOUT    256
#define LN_EPS  1e-5f
#define MAX_ROWS 65536
#define NCHUNKS 8

// Scratch: fused (node + pooled) vectors, [N, 512], fp16.
__device__ __half g_fused[(size_t)MAX_ROWS * HDIM];
// Transposed + fp16-rounded out_W: [256, 512] (n-major, k-contiguous).
__device__ __half g_Bt[(size_t)HOUT * HDIM];

// ---------------------------------------------------------------------------
// Helpers
// ---------------------------------------------------------------------------
__device__ __forceinline__ uint32_t smem_u32(const void* p) {
    uint32_t a;
    asm("{ .reg .u64 t; cvta.to.shared.u64 t, %1; cvt.u32.u64 %0, t; }" : "=r"(a) : "l"(p));
    return a;
}

__device__ __forceinline__ void mma_fp16(float* d, const uint32_t* a, const uint32_t* b) {
    asm volatile(
        "mma.sync.aligned.m16n8k16.row.col.f32.f16.f16.f32 "
        "{%0,%1,%2,%3}, {%4,%5,%6,%7}, {%8,%9}, {%0,%1,%2,%3};"
        : "+f"(d[0]), "+f"(d[1]), "+f"(d[2]), "+f"(d[3])
        : "r"(a[0]), "r"(a[1]), "r"(a[2]), "r"(a[3]), "r"(b[0]), "r"(b[1]));
}

__device__ __forceinline__ void cp_async16(uint32_t dst, const void* src) {
    asm volatile("cp.async.cg.shared.global [%0], [%1], 16;"
                 :: "r"(dst), "l"(src) : "memory");
}
#define CP_COMMIT() asm volatile("cp.async.commit_group;" ::: "memory")
#define CP_WAIT(n)  asm volatile("cp.async.wait_group %0;" :: "n"(n) : "memory")

// ---------------------------------------------------------------------------
// Kernel A (v6): LayerNorm + attention pooling — R13 config, + row offset.
// ---------------------------------------------------------------------------
__global__ __launch_bounds__(256) void ln_attn_v6_kernel(
    const float* __restrict__ x,
    const float* __restrict__ gamma,
    const float* __restrict__ beta,
    const float* __restrict__ attnW,
    int row0)
{
    __shared__ float s_red[2][4][26];
    __shared__ float s_k[2][8];
    __shared__ float s_K[2];

    const int tid  = threadIdx.x;
    const int w    = tid >> 5;
    const int lane = tid & 31;
    const int rloc = w >> 2;
    const int slab = w & 3;
    const size_t row = (size_t)row0 + blockIdx.x * 2 + rloc;
    const int c4  = slab * 32 + lane;
    const int col = c4 * 4;

    const float4* xr = reinterpret_cast<const float4*>(x + row * SEQ * HDIM);
    const float4 gv = *reinterpret_cast<const float4*>(gamma + col);
    const float4 wn = *reinterpret_cast<const float4*>(attnW + HDIM + col);
    float4 gw;
    gw.x = gv.x * wn.x; gw.y = gv.y * wn.y; gw.z = gv.z * wn.z; gw.w = gv.w * wn.w;

    float4 xv[SEQ];
    float vals[32];
    #pragma unroll
    for (int t = 0; t < SEQ; t++) {
        const float4 v = xr[t * (HDIM / 4) + c4];
        xv[t] = v;
        vals[t]      = (v.x + v.y) + (v.z + v.w);
        vals[8 + t]  = (v.x * v.x + v.y * v.y) + (v.z * v.z + v.w * v.w);
        vals[16 + t] = (gw.x * v.x + gw.y * v.y) + (gw.z * v.z + gw.w * v.w);
    }
    vals[24] = (gw.x + gw.y) + (gw.z + gw.w);
    #pragma unroll
    for (int j = 25; j < 32; j++) vals[j] = 0.f;

    #pragma unroll
    for (int bit = 16; bit >= 1; bit >>= 1) {
        #pragma unroll
        for (int j = 0; j < bit; j++) {
            const bool hi = (lane & bit) != 0;
            const float keep = hi ? vals[j + bit] : vals[j];
            const float send = hi ? vals[j] : vals[j + bit];
            vals[j] = keep + __shfl_xor_sync(0xffffffffu, send, bit);
        }
    }

    if (lane < 25) s_red[rloc][slab][lane] = vals[0];
    __syncthreads();

    if ((w & 3) == 0) {
        const int r = rloc;
        float v = 0.f;
        if (lane < 25) {
            #pragma unroll
            for (int sl = 0; sl < 4; sl++) v += s_red[r][sl][lane];
        }
        const int t = lane & 7;
        const float S  = __shfl_sync(0xffffffffu, v, t);
        const float Q  = __shfl_sync(0xffffffffu, v, 8 + t);
        const float P  = __shfl_sync(0xffffffffu, v, 16 + t);
        const float S1 = __shfl_sync(0xffffffffu, v, 24);

        const float m    = S * (1.f / HDIM);
        const float var  = Q * (1.f / HDIM) - m * m;
        const float rstd = rsqrtf(var + LN_EPS);

        float logit = (lane >= 1 && lane < 8) ? rstd * (P - m * S1) : -1e30f;

        float mx = logit;
        mx = fmaxf(mx, __shfl_xor_sync(0xffffffffu, mx, 1));
        mx = fmaxf(mx, __shfl_xor_sync(0xffffffffu, mx, 2));
        mx = fmaxf(mx, __shfl_xor_sync(0xffffffffu, mx, 4));
        const float e = __expf(logit - mx);
        float se = e;
        se += __shfl_xor_sync(0xffffffffu, se, 1);
        se += __shfl_xor_sync(0xffffffffu, se, 2);
        se += __shfl_xor_sync(0xffffffffu, se, 4);
        const float a = e / se;

        const float k = (lane == 0) ? rstd : a * rstd;
        float Km = k * m;
        Km += __shfl_xor_sync(0xffffffffu, Km, 1);
        Km += __shfl_xor_sync(0xffffffffu, Km, 2);
        Km += __shfl_xor_sync(0xffffffffu, Km, 4);

        if (lane < 8) s_k[r][lane] = k;
        if (lane == 0) s_K[r] = Km;
    }
    __syncthreads();

    const float Kc = s_K[rloc];
    float4 acc = make_float4(0.f, 0.f, 0.f, 0.f);
    #pragma unroll
    for (int t = 0; t < SEQ; t++) {
        const float k = s_k[rloc][t];
        acc.x += k * xv[t].x;
        acc.y += k * xv[t].y;
        acc.z += k * xv[t].z;
        acc.w += k * xv[t].w;
    }
    const float4 bv = *reinterpret_cast<const float4*>(beta + col);
    const __half2 o0 = __floats2half2_rn(gv.x * (acc.x - Kc) + 2.f * bv.x,
                                         gv.y * (acc.y - Kc) + 2.f * bv.y);
    const __half2 o1 = __floats2half2_rn(gv.z * (acc.z - Kc) + 2.f * bv.z,
                                         gv.w * (acc.w - Kc) + 2.f * bv.w);
    uint2 o;
    o.x = *reinterpret_cast<const uint32_t*>(&o0);
    o.y = *reinterpret_cast<const uint32_t*>(&o1);
    *reinterpret_cast<uint2*>(&g_fused[row * HDIM + col]) = o;
}

// ---------------------------------------------------------------------------
// Transpose out_W [512,256] -> g_Bt [256,512] fp16.
// ---------------------------------------------------------------------------
__global__ __launch_bounds__(256) void transpose_B_kernel(const float* __restrict__ B) {
    __shared__ float tile[32][33];
    const int n0 = blockIdx.x * 32;
    const int k0 = blockIdx.y * 32;
    const int tx = threadIdx.x & 31;
    const int ty = threadIdx.x >> 5;
    #pragma unroll
    for (int i = 0; i < 32; i += 8)
        tile[ty + i][tx] = B[(size_t)(k0 + ty + i) * HOUT + n0 + tx];
    __syncthreads();
    #pragma unroll
    for (int i = 0; i < 32; i += 8) {
        g_Bt[(size_t)(n0 + ty + i) * HDIM + k0 + tx] = __float2half_rn(tile[tx][ty + i]);
    }
}

// ---------------------------------------------------------------------------
// Kernel B: fp16 mma.sync GEMM — R13 config, + row offset.
// ---------------------------------------------------------------------------
#define BM 128
#define BN 128
#define BKH 32
#define STAGES 3
#define A_STAGE_BYTES (BM * BKH * 2)
#define B_STAGE_BYTES (BN * BKH * 2)
#define STAGE_BYTES   (A_STAGE_BYTES + B_STAGE_BYTES)
#define GEMM_SMEM     (STAGES * STAGE_BYTES)
#define NCH           (HDIM / BKH)

__global__ __launch_bounds__(256, 2) void gemm_fp16_kernel(
    const float* __restrict__ bias,
    float* __restrict__ C,
    int row0)
{
    extern __shared__ char smem[];

    const int tid  = threadIdx.x;
    const int lane = tid & 31;
    const int wid  = tid >> 5;
    const int warp_m = wid & 3;
    const int warp_n = wid >> 2;
    const int g  = lane >> 2;
    const int tg = lane & 3;

    const int bn = blockIdx.x;
    const int row_tile = row0 + (int)blockIdx.y * BM;

    const __half* Ag = g_fused + (size_t)row_tile * HDIM;
    const __half* Bg = g_Bt + (size_t)bn * BN * HDIM;

    const uint32_t smem_base = smem_u32(smem);

    const int st_row = tid >> 1;
    const int st_u   = (tid & 1) * 2;

    float acc[2][8][4];
    #pragma unroll
    for (int mt = 0; mt < 2; mt++)
        #pragma unroll
        for (int nt = 0; nt < 8; nt++)
            #pragma unroll
            for (int i = 0; i < 4; i++) acc[mt][nt][i] = 0.f;

    auto stage_chunk = [&](int kchunk, int st) {
        const uint32_t sA = smem_base + (uint32_t)(st * STAGE_BYTES);
        const uint32_t sB = sA + A_STAGE_BYTES;
        const __half* srcA = Ag + (size_t)st_row * HDIM + kchunk * BKH + st_u * 8;
        const __half* srcB = Bg + (size_t)st_row * HDIM + kchunk * BKH + st_u * 8;
        #pragma unroll
        for (int j = 0; j < 2; j++)
            cp_async16(sA + (uint32_t)(st_row * 4 + st_u + j) * 16u, srcA + j * 8);
        #pragma unroll
        for (int j = 0; j < 2; j++)
            cp_async16(sB + (uint32_t)(st_row * 4 + st_u + j) * 16u, srcB + j * 8);
    };

    stage_chunk(0, 0); CP_COMMIT();
    stage_chunk(1, 1); CP_COMMIT();

    #pragma unroll
    for (int k = 0; k < NCH; k++) {
        const int cur = k % STAGES;

        CP_WAIT(1);
        __syncthreads();

        if (k + 2 < NCH) stage_chunk(k + 2, (k + 2) % STAGES);
        CP_COMMIT();

        const char* Abuf = smem + cur * STAGE_BYTES;
        const char* Bbuf = Abuf + A_STAGE_BYTES;

        uint32_t aw[2][2][4];
        #pragma unroll
        for (int mt = 0; mt < 2; mt++) {
            #pragma unroll
            for (int h = 0; h < 2; h++) {
                const int r = warp_m * 32 + mt * 16 + g + h * 8;
                const uint4 v = *reinterpret_cast<const uint4*>(
                    Abuf + (r * 4 + tg) * 16);
                aw[mt][h][0] = v.x; aw[mt][h][1] = v.y;
                aw[mt][h][2] = v.z; aw[mt][h][3] = v.w;
            }
        }
        #pragma unroll
        for (int half = 0; half < 2; half++) {
            uint32_t bw[4][4];
            #pragma unroll
            for (int q = 0; q < 4; q++) {
                const int n = warp_n * 64 + (half * 4 + q) * 8 + g;
                const uint4 v = *reinterpret_cast<const uint4*>(
                    Bbuf + (n * 4 + tg) * 16);
                bw[q][0] = v.x; bw[q][1] = v.y; bw[q][2] = v.z; bw[q][3] = v.w;
            }
            #pragma unroll
            for (int grp = 0; grp < 2; grp++) {
                #pragma unroll
                for (int mt = 0; mt < 2; mt++) {
                    #pragma unroll
                    for (int q = 0; q < 4; q++) {
                        const int nt = half * 4 + q;
                        uint32_t a[4] = { aw[mt][0][grp * 2 + 0],
                                          aw[mt][1][grp * 2 + 0],
                                          aw[mt][0][grp * 2 + 1],
                                          aw[mt][1][grp * 2 + 1] };
                        uint32_t b[2] = { bw[q][grp * 2 + 0],
                                          bw[q][grp * 2 + 1] };
                        mma_fp16(acc[mt][nt], a, b);
                    }
                }
            }
        }
    }

    const int row_base = row_tile + warp_m * 32;
    const int col_base = bn * BN + warp_n * 64;
    #pragma unroll
    for (int mt = 0; mt < 2; mt++) {
        #pragma unroll
        for (int nt = 0; nt < 8; nt++) {
            const int r0 = row_base + mt * 16 + g;
            const int c0 = col_base + nt * 8 + 2 * tg;
            const float2 bb = *reinterpret_cast<const float2*>(bias + c0);
            float2 o0, o1;
            o0.x = fmaxf(acc[mt][nt][0] + bb.x, 0.f);
            o0.y = fmaxf(acc[mt][nt][1] + bb.y, 0.f);
            o1.x = fmaxf(acc[mt][nt][2] + bb.x, 0.f);
            o1.y = fmaxf(acc[mt][nt][3] + bb.y, 0.f);
            *reinterpret_cast<float2*>(C + (size_t)r0 * HOUT + c0) = o0;
            *reinterpret_cast<float2*>(C + (size_t)(r0 + 8) * HOUT + c0) = o1;
        }
    }
}

// ---------------------------------------------------------------------------
// Launch: chunked dual-stream pipeline. gemm(chunk c) on stream sB overlaps
// ln(chunk c+1) on the main stream. Fork/join via events (capture-legal).
// Streams/events created once on the uncaptured correctness call.
// ---------------------------------------------------------------------------
extern "C" void kernel_launch(void* const* d_in, const int* in_sizes, int n_in,
                              void* d_out, int out_size) {
    const float* x     = (const float*)d_in[0];   // [N, 8, 512]
    const float* gamma = (const float*)d_in[1];   // [512]
    const float* beta  = (const float*)d_in[2];   // [512]
    const float* attnW = (const float*)d_in[3];   // [1024, 1]
    // d_in[4] = attn_b: cancels in softmax.
    const float* outW  = (const float*)d_in[5];   // [512, 256]
    const float* outb  = (const float*)d_in[6];   // [256]
    float* out = (float*)d_out;                   // [N, 256]

    const int n = in_sizes[0] / (SEQ * HDIM);
    const int chunk = n / NCHUNKS;

    static cudaStream_t sB = nullptr;
    static cudaEvent_t evFork, evLn[NCHUNKS], evJoin;
    if (sB == nullptr) {
        cudaStreamCreateWithFlags(&sB, cudaStreamNonBlocking);
        cudaEventCreateWithFlags(&evFork, cudaEventDisableTiming);
        cudaEventCreateWithFlags(&evJoin, cudaEventDisableTiming);
        for (int c = 0; c < NCHUNKS; c++)
            cudaEventCreateWithFlags(&evLn[c], cudaEventDisableTiming);
        cudaFuncSetAttribute(gemm_fp16_kernel,
                             cudaFuncAttributeMaxDynamicSharedMemorySize, GEMM_SMEM);
    }

    // Fork sB from the main (captured) stream, run the B transpose there.
    cudaEventRecord(evFork, 0);
    cudaStreamWaitEvent(sB, evFork, 0);
    transpose_B_kernel<<<dim3(HOUT / 32, HDIM / 32), 256, 0, sB>>>(outW);

    for (int c = 0; c < NCHUNKS; c++) {
        const int row0 = c * chunk;
        ln_attn_v6_kernel<<<chunk / 2, 256>>>(x, gamma, beta, attnW, row0);
        cudaEventRecord(evLn[c], 0);
        cudaStreamWaitEvent(sB, evLn[c], 0);
        dim3 grid(HOUT / BN, chunk / BM);
        gemm_fp16_kernel<<<grid, 256, GEMM_SMEM, sB>>>(outb, out, row0);
    }

    // Join sB back into the main stream.
    cudaEventRecord(evJoin, sB);
    cudaStreamWaitEvent(0, evJoin, 0);
}

// round 16
// speedup vs baseline: 1.1664x; 1.0992x over previous
#include <cuda_runtime.h>
#include <cuda_fp16.h>
#include <cstdint>

#define SEQ     8
#define HDIM    512
#define HOUT    256
#define LN_EPS  1e-5f
#define MAX_ROWS 65536

// Scratch: fused (node + pooled) vectors, [N, 512], fp16.
__device__ __half g_fused[(size_t)MAX_ROWS * HDIM];
// Transposed + fp16-rounded out_W: [256, 512] (n-major, k-contiguous).
__device__ __half g_Bt[(size_t)HOUT * HDIM];

// ---------------------------------------------------------------------------
// Helpers
// ---------------------------------------------------------------------------
__device__ __forceinline__ uint32_t smem_u32(const void* p) {
    uint32_t a;
    asm("{ .reg .u64 t; cvta.to.shared.u64 t, %1; cvt.u32.u64 %0, t; }" : "=r"(a) : "l"(p));
    return a;
}

__device__ __forceinline__ void mma_fp16(float* d, const uint32_t* a, const uint32_t* b) {
    asm volatile(
        "mma.sync.aligned.m16n8k16.row.col.f32.f16.f16.f32 "
        "{%0,%1,%2,%3}, {%4,%5,%6,%7}, {%8,%9}, {%0,%1,%2,%3};"
        : "+f"(d[0]), "+f"(d[1]), "+f"(d[2]), "+f"(d[3])
        : "r"(a[0]), "r"(a[1]), "r"(a[2]), "r"(a[3]), "r"(b[0]), "r"(b[1]));
}

__device__ __forceinline__ void cp_async16(uint32_t dst, const void* src) {
    asm volatile("cp.async.cg.shared.global [%0], [%1], 16;"
                 :: "r"(dst), "l"(src) : "memory");
}
#define CP_COMMIT() asm volatile("cp.async.commit_group;" ::: "memory")
#define CP_WAIT(n)  asm volatile("cp.async.wait_group %0;" :: "n"(n) : "memory")

// ---------------------------------------------------------------------------
// Kernel A (v6): LayerNorm + attention pooling — frozen R13 config.
// ---------------------------------------------------------------------------
__global__ __launch_bounds__(256) void ln_attn_v6_kernel(
    const float* __restrict__ x,
    const float* __restrict__ gamma,
    const float* __restrict__ beta,
    const float* __restrict__ attnW)
{
    __shared__ float s_red[2][4][26];
    __shared__ float s_k[2][8];
    __shared__ float s_K[2];

    const int tid  = threadIdx.x;
    const int w    = tid >> 5;
    const int lane = tid & 31;
    const int rloc = w >> 2;
    const int slab = w & 3;
    const size_t row = (size_t)blockIdx.x * 2 + rloc;
    const int c4  = slab * 32 + lane;
    const int col = c4 * 4;

    const float4* xr = reinterpret_cast<const float4*>(x + row * SEQ * HDIM);
    const float4 gv = *reinterpret_cast<const float4*>(gamma + col);
    const float4 wn = *reinterpret_cast<const float4*>(attnW + HDIM + col);
    float4 gw;
    gw.x = gv.x * wn.x; gw.y = gv.y * wn.y; gw.z = gv.z * wn.z; gw.w = gv.w * wn.w;

    float4 xv[SEQ];
    float vals[32];
    #pragma unroll
    for (int t = 0; t < SEQ; t++) {
        const float4 v = xr[t * (HDIM / 4) + c4];
        xv[t] = v;
        vals[t]      = (v.x + v.y) + (v.z + v.w);
        vals[8 + t]  = (v.x * v.x + v.y * v.y) + (v.z * v.z + v.w * v.w);
        vals[16 + t] = (gw.x * v.x + gw.y * v.y) + (gw.z * v.z + gw.w * v.w);
    }
    vals[24] = (gw.x + gw.y) + (gw.z + gw.w);
    #pragma unroll
    for (int j = 25; j < 32; j++) vals[j] = 0.f;

    #pragma unroll
    for (int bit = 16; bit >= 1; bit >>= 1) {
        #pragma unroll
        for (int j = 0; j < bit; j++) {
            const bool hi = (lane & bit) != 0;
            const float keep = hi ? vals[j + bit] : vals[j];
            const float send = hi ? vals[j] : vals[j + bit];
            vals[j] = keep + __shfl_xor_sync(0xffffffffu, send, bit);
        }
    }

    if (lane < 25) s_red[rloc][slab][lane] = vals[0];
    __syncthreads();

    if ((w & 3) == 0) {
        const int r = rloc;
        float v = 0.f;
        if (lane < 25) {
            #pragma unroll
            for (int sl = 0; sl < 4; sl++) v += s_red[r][sl][lane];
        }
        const int t = lane & 7;
        const float S  = __shfl_sync(0xffffffffu, v, t);
        const float Q  = __shfl_sync(0xffffffffu, v, 8 + t);
        const float P  = __shfl_sync(0xffffffffu, v, 16 + t);
        const float S1 = __shfl_sync(0xffffffffu, v, 24);

        const float m    = S * (1.f / HDIM);
        const float var  = Q * (1.f / HDIM) - m * m;
        const float rstd = rsqrtf(var + LN_EPS);

        float logit = (lane >= 1 && lane < 8) ? rstd * (P - m * S1) : -1e30f;

        float mx = logit;
        mx = fmaxf(mx, __shfl_xor_sync(0xffffffffu, mx, 1));
        mx = fmaxf(mx, __shfl_xor_sync(0xffffffffu, mx, 2));
        mx = fmaxf(mx, __shfl_xor_sync(0xffffffffu, mx, 4));
        const float e = __expf(logit - mx);
        float se = e;
        se += __shfl_xor_sync(0xffffffffu, se, 1);
        se += __shfl_xor_sync(0xffffffffu, se, 2);
        se += __shfl_xor_sync(0xffffffffu, se, 4);
        const float a = e / se;

        const float k = (lane == 0) ? rstd : a * rstd;
        float Km = k * m;
        Km += __shfl_xor_sync(0xffffffffu, Km, 1);
        Km += __shfl_xor_sync(0xffffffffu, Km, 2);
        Km += __shfl_xor_sync(0xffffffffu, Km, 4);

        if (lane < 8) s_k[r][lane] = k;
        if (lane == 0) s_K[r] = Km;
    }
    __syncthreads();

    const float Kc = s_K[rloc];
    float4 acc = make_float4(0.f, 0.f, 0.f, 0.f);
    #pragma unroll
    for (int t = 0; t < SEQ; t++) {
        const float k = s_k[rloc][t];
        acc.x += k * xv[t].x;
        acc.y += k * xv[t].y;
        acc.z += k * xv[t].z;
        acc.w += k * xv[t].w;
    }
    const float4 bv = *reinterpret_cast<const float4*>(beta + col);
    const __half2 o0 = __floats2half2_rn(gv.x * (acc.x - Kc) + 2.f * bv.x,
                                         gv.y * (acc.y - Kc) + 2.f * bv.y);
    const __half2 o1 = __floats2half2_rn(gv.z * (acc.z - Kc) + 2.f * bv.z,
                                         gv.w * (acc.w - Kc) + 2.f * bv.w);
    uint2 o;
    o.x = *reinterpret_cast<const uint32_t*>(&o0);
    o.y = *reinterpret_cast<const uint32_t*>(&o1);
    *reinterpret_cast<uint2*>(&g_fused[row * HDIM + col]) = o;
}

// ---------------------------------------------------------------------------
// Transpose out_W [512,256] -> g_Bt [256,512] fp16.
// ---------------------------------------------------------------------------
__global__ __launch_bounds__(256) void transpose_B_kernel(const float* __restrict__ B) {
    __shared__ float tile[32][33];
    const int n0 = blockIdx.x * 32;
    const int k0 = blockIdx.y * 32;
    const int tx = threadIdx.x & 31;
    const int ty = threadIdx.x >> 5;
    #pragma unroll
    for (int i = 0; i < 32; i += 8)
        tile[ty + i][tx] = B[(size_t)(k0 + ty + i) * HOUT + n0 + tx];
    __syncthreads();
    #pragma unroll
    for (int i = 0; i < 32; i += 8) {
        g_Bt[(size_t)(n0 + ty + i) * HDIM + k0 + tx] = __float2half_rn(tile[tx][ty + i]);
    }
}

// ---------------------------------------------------------------------------
// Kernel B (v8): fp16 mma.sync GEMM. A staged via 3-stage cp.async + LDS
// (as R13); B fragments loaded DIRECTLY via LDG from L2-resident g_Bt
// (mechanic validated in the R14 fused kernel). Removes all B STS + B LDS:
// per-CTA crossbar traffic drops ~65%.
// ---------------------------------------------------------------------------
#define BM 128
#define BN 128
#define BKH 32
#define STAGES 3
#define A_STAGE_BYTES (BM * BKH * 2)              // 8 KB
#define GEMM_SMEM     (STAGES * A_STAGE_BYTES)    // 24 KB
#define NCH           (HDIM / BKH)                // 16

__global__ __launch_bounds__(256, 2) void gemm_v8_kernel(
    const float* __restrict__ bias,
    float* __restrict__ C)
{
    extern __shared__ char smem[];

    const int tid  = threadIdx.x;
    const int lane = tid & 31;
    const int wid  = tid >> 5;
    const int warp_m = wid & 3;            // 0..3 -> M offset *32
    const int warp_n = wid >> 2;           // 0..1 -> N offset *64
    const int g  = lane >> 2;              // 0..7
    const int tg = lane & 3;               // 0..3

    const int bn = blockIdx.x;
    const int bm = (int)(gridDim.y - 1) - (int)blockIdx.y;   // newest rows first

    const __half* Ag = g_fused + (size_t)bm * BM * HDIM;
    const __half* Bg = g_Bt + (size_t)bn * BN * HDIM;

    const uint32_t smem_base = smem_u32(smem);

    // A staging: thread t -> row t>>1, 16B unit t&1 (+2 per j). Row = 4 units.
    const int st_row = tid >> 1;
    const int st_u   = (tid & 1) * 2;

    float acc[2][8][4];
    #pragma unroll
    for (int mt = 0; mt < 2; mt++)
        #pragma unroll
        for (int nt = 0; nt < 8; nt++)
            #pragma unroll
            for (int i = 0; i < 4; i++) acc[mt][nt][i] = 0.f;

    auto stage_A = [&](int kchunk, int st) {
        const uint32_t sA = smem_base + (uint32_t)(st * A_STAGE_BYTES);
        const __half* srcA = Ag + (size_t)st_row * HDIM + kchunk * BKH + st_u * 8;
        #pragma unroll
        for (int j = 0; j < 2; j++)
            cp_async16(sA + (uint32_t)(st_row * 4 + st_u + j) * 16u, srcA + j * 8);
    };

    stage_A(0, 0); CP_COMMIT();
    stage_A(1, 1); CP_COMMIT();

    // Per-warp B fragment base (column group): warp_n picks 64 of 128 cols.
    #pragma unroll
    for (int k = 0; k < NCH; k++) {
        const int cur = k % STAGES;

        // Issue B half-0 LDGs first: latency overlaps the A-pipeline wait.
        uint32_t bw0[4][4];
        #pragma unroll
        for (int q = 0; q < 4; q++) {
            const int n = warp_n * 64 + q * 8 + g;
            const uint4 v = *reinterpret_cast<const uint4*>(
                Bg + (size_t)n * HDIM + k * BKH + tg * 8);
            bw0[q][0] = v.x; bw0[q][1] = v.y; bw0[q][2] = v.z; bw0[q][3] = v.w;
        }

        CP_WAIT(1);
        __syncthreads();   // slot (k+2)%3 fully consumed in iteration k-1

        if (k + 2 < NCH) stage_A(k + 2, (k + 2) % STAGES);
        CP_COMMIT();

        const char* Abuf = smem + cur * A_STAGE_BYTES;

        // A fragments: 4 x LDS.128.
        uint32_t aw[2][2][4];
        #pragma unroll
        for (int mt = 0; mt < 2; mt++) {
            #pragma unroll
            for (int h = 0; h < 2; h++) {
                const int r = warp_m * 32 + mt * 16 + g + h * 8;
                const uint4 v = *reinterpret_cast<const uint4*>(
                    Abuf + (r * 4 + tg) * 16);
                aw[mt][h][0] = v.x; aw[mt][h][1] = v.y;
                aw[mt][h][2] = v.z; aw[mt][h][3] = v.w;
            }
        }

        // Issue B half-1 LDGs before half-0 MMAs so they overlap compute.
        uint32_t bw1[4][4];
        #pragma unroll
        for (int q = 0; q < 4; q++) {
            const int n = warp_n * 64 + (4 + q) * 8 + g;
            const uint4 v = *reinterpret_cast<const uint4*>(
                Bg + (size_t)n * HDIM + k * BKH + tg * 8);
            bw1[q][0] = v.x; bw1[q][1] = v.y; bw1[q][2] = v.z; bw1[q][3] = v.w;
        }

        #pragma unroll
        for (int grp = 0; grp < 2; grp++) {
            #pragma unroll
            for (int mt = 0; mt < 2; mt++) {
                #pragma unroll
                for (int q = 0; q < 4; q++) {
                    uint32_t a[4] = { aw[mt][0][grp * 2 + 0],
                                      aw[mt][1][grp * 2 + 0],
                                      aw[mt][0][grp * 2 + 1],
                                      aw[mt][1][grp * 2 + 1] };
                    uint32_t b[2] = { bw0[q][grp * 2 + 0],
                                      bw0[q][grp * 2 + 1] };
                    mma_fp16(acc[mt][q], a, b);
                }
            }
        }
        #pragma unroll
        for (int grp = 0; grp < 2; grp++) {
            #pragma unroll
            for (int mt = 0; mt < 2; mt++) {
                #pragma unroll
                for (int q = 0; q < 4; q++) {
                    uint32_t a[4] = { aw[mt][0][grp * 2 + 0],
                                      aw[mt][1][grp * 2 + 0],
                                      aw[mt][0][grp * 2 + 1],
                                      aw[mt][1][grp * 2 + 1] };
                    uint32_t b[2] = { bw1[q][grp * 2 + 0],
                                      bw1[q][grp * 2 + 1] };
                    mma_fp16(acc[mt][4 + q], a, b);
                }
            }
        }
    }

    // Epilogue: bias + relu.
    const int row_base = bm * BM + warp_m * 32;
    const int col_base = bn * BN + warp_n * 64;
    #pragma unroll
    for (int mt = 0; mt < 2; mt++) {
        #pragma unroll
        for (int nt = 0; nt < 8; nt++) {
            const int r0 = row_base + mt * 16 + g;
            const int c0 = col_base + nt * 8 + 2 * tg;
            const float2 bb = *reinterpret_cast<const float2*>(bias + c0);
            float2 o0, o1;
            o0.x = fmaxf(acc[mt][nt][0] + bb.x, 0.f);
            o0.y = fmaxf(acc[mt][nt][1] + bb.y, 0.f);
            o1.x = fmaxf(acc[mt][nt][2] + bb.x, 0.f);
            o1.y = fmaxf(acc[mt][nt][3] + bb.y, 0.f);
            *reinterpret_cast<float2*>(C + (size_t)r0 * HOUT + c0) = o0;
            *reinterpret_cast<float2*>(C + (size_t)(r0 + 8) * HOUT + c0) = o1;
        }
    }
}

// ---------------------------------------------------------------------------
extern "C" void kernel_launch(void* const* d_in, const int* in_sizes, int n_in,
                              void* d_out, int out_size) {
    const float* x     = (const float*)d_in[0];   // [N, 8, 512]
    const float* gamma = (const float*)d_in[1];   // [512]
    const float* beta  = (const float*)d_in[2];   // [512]
    const float* attnW = (const float*)d_in[3];   // [1024, 1]
    // d_in[4] = attn_b: cancels in softmax.
    const float* outW  = (const float*)d_in[5];   // [512, 256]
    const float* outb  = (const float*)d_in[6];   // [256]
    float* out = (float*)d_out;                   // [N, 256]

    const int n = in_sizes[0] / (SEQ * HDIM);

    cudaFuncSetAttribute(gemm_v8_kernel,
                         cudaFuncAttributeMaxDynamicSharedMemorySize, GEMM_SMEM);

    transpose_B_kernel<<<dim3(HOUT / 32, HDIM / 32), 256>>>(outW);
    ln_attn_v6_kernel<<<n / 2, 256>>>(x, gamma, beta, attnW);

    dim3 grid(HOUT / BN, n / BM);
    gemm_v8_kernel<<<grid, 256, GEMM_SMEM>>>(outb, out);
}